// round 3
// baseline (speedup 1.0000x reference)
#include <cuda_runtime.h>
#include <cuda_fp16.h>

#define SEQ    256
#define VOC    96
#define DEND   (SEQ * VOC)           // 24576 dendrites
#define ZROW   DEND                  // all-zero row for masked positions
#define LANES  12                    // uint4 (8 halves) per lane: 12*16B = 192B row
#define CHUNKS 32
#define CPOS   (SEQ / CHUNKS)        // 8 positions per chunk
#define ROWU4  (VOC / 8)             // 12 uint4 per row

// fp16 transposed log-weight table: T[d][v] = log(max(2*sigmoid(raw[v][d]), 1e-8))
// (DEND+1) rows of VOC halves; last row zeros. ~4.7 MB -> L2 resident.
__device__ __align__(16) __half g_logw[(DEND + 1) * VOC];

// ---------------------------------------------------------------------------
// Kernel A: fused sigmoid/log + transpose (coalesced both sides via smem tile)
// ---------------------------------------------------------------------------
__global__ void prep_kernel(const float* __restrict__ raw) {
    __shared__ float tile[32][33];
    const int d0 = blockIdx.x * 32;
    const int v0 = blockIdx.y * 32;
    const int tx = threadIdx.x, ty = threadIdx.y;

    #pragma unroll
    for (int i = ty; i < 32; i += 8) {
        float x = raw[(v0 + i) * DEND + (d0 + tx)];
        float w = 2.0f * __frcp_rn(1.0f + __expf(-x));
        w = fmaxf(w, 1e-8f);
        tile[i][tx] = __logf(w);
    }
    __syncthreads();
    #pragma unroll
    for (int i = ty; i < 32; i += 8) {
        g_logw[(d0 + i) * VOC + (v0 + tx)] = __float2half_rn(tile[tx][i]);
    }
    if (blockIdx.x == 0 && blockIdx.y == 0 && ty == 0) {
        #pragma unroll
        for (int k = tx; k < VOC; k += 32)
            g_logw[ZROW * VOC + k] = __float2half_rn(0.0f);
    }
}

// ---------------------------------------------------------------------------
// Kernel B: one sample per block, 384 threads.
// thread t: chunk = t/12 (8 seq positions), lane = t%12 (8 vocab entries, 16B).
// HADD2 accumulation (chains of <=5 adds -> fp16 safe), smem reduce, exp.
// ---------------------------------------------------------------------------
__global__ void __launch_bounds__(LANES * CHUNKS)
gather_kernel(const int* __restrict__ chars,
              float* __restrict__ out) {
    __shared__ int    offs[SEQ];                     // uint4-unit row offsets
    __shared__ float4 part[CHUNKS][LANES][2];        // 12 KB partials
    __shared__ int    nact_s;

    const int b = blockIdx.x;
    const int t = threadIdx.x;                       // 0..383

    if (t == 0) nact_s = 0;
    __syncthreads();

    if (t < SEQ) {
        const int c = chars[b * SEQ + t];
        const bool act = (c > 0);
        const int dend = act ? (t * VOC + c - 1) : ZROW;
        offs[t] = dend * ROWU4;
        const unsigned m = __ballot_sync(0xffffffffu, act);
        if ((t & 31) == 0) atomicAdd(&nact_s, __popc(m));
    }
    __syncthreads();

    const int lane  = t % LANES;
    const int chunk = t / LANES;
    const int s0    = chunk * CPOS;
    const uint4* __restrict__ base = (const uint4*)g_logw;

    const __half2 z = __float2half2_rn(0.0f);
    __half2 A0 = z, A1 = z, A2 = z, A3 = z;
    __half2 B0 = z, B1 = z, B2 = z, B3 = z;

    #pragma unroll
    for (int i = 0; i < CPOS; i += 2) {
        const int oa = offs[s0 + i];
        const int ob = offs[s0 + i + 1];
        const uint4 ua = base[oa + lane];
        const uint4 ub = base[ob + lane];
        A0 = __hadd2(A0, *(const __half2*)&ua.x);
        A1 = __hadd2(A1, *(const __half2*)&ua.y);
        A2 = __hadd2(A2, *(const __half2*)&ua.z);
        A3 = __hadd2(A3, *(const __half2*)&ua.w);
        B0 = __hadd2(B0, *(const __half2*)&ub.x);
        B1 = __hadd2(B1, *(const __half2*)&ub.y);
        B2 = __hadd2(B2, *(const __half2*)&ub.z);
        B3 = __hadd2(B3, *(const __half2*)&ub.w);
    }

    const float2 f0 = __half22float2(__hadd2(A0, B0));
    const float2 f1 = __half22float2(__hadd2(A1, B1));
    const float2 f2 = __half22float2(__hadd2(A2, B2));
    const float2 f3 = __half22float2(__hadd2(A3, B3));
    part[chunk][lane][0] = make_float4(f0.x, f0.y, f1.x, f1.y);
    part[chunk][lane][1] = make_float4(f2.x, f2.y, f3.x, f3.y);
    __syncthreads();

    // Reduce: 24 threads, each owns one vocab quad (float4) across 32 chunks.
    if (t < 2 * LANES) {
        const int lane2 = t >> 1;       // which 16B lane
        const int half  = t & 1;        // which float4 of the lane
        float sx = 0.f, sy = 0.f, sz = 0.f, sw = 0.f;
        #pragma unroll
        for (int k = 0; k < CHUNKS; k++) {
            const float4 v = part[k][lane2][half];
            sx += v.x; sy += v.y; sz += v.z; sw += v.w;
        }
        const float inv = __frcp_rn((float)max(nact_s, 1));
        float4 r;
        r.x = __expf(sx * inv);
        r.y = __expf(sy * inv);
        r.z = __expf(sz * inv);
        r.w = __expf(sw * inv);
        ((float4*)(out + b * VOC))[t] = r;
    }
}

// ---------------------------------------------------------------------------
extern "C" void kernel_launch(void* const* d_in, const int* in_sizes, int n_in,
                              void* d_out, int out_size) {
    const int*   chars = (const int*)d_in[0];     // (B, 256) int32
    const float* raw   = (const float*)d_in[1];   // (96, 24576) float32
    float*       out   = (float*)d_out;           // (B, 96) float32

    const int batch = in_sizes[0] / SEQ;

    dim3 pgrid(DEND / 32, VOC / 32);              // (768, 3)
    dim3 pblk(32, 8);
    prep_kernel<<<pgrid, pblk>>>(raw);

    gather_kernel<<<batch, LANES * CHUNKS>>>(chars, out);
}

// round 4
// speedup vs baseline: 1.0135x; 1.0135x over previous
#include <cuda_runtime.h>
#include <cuda_fp16.h>

#define SEQ    256
#define VOC    96
#define VPAD   128                   // padded row width in halves (256 B)
#define DEND   (SEQ * VOC)           // 24576 dendrites
#define ZROW   DEND                  // all-zero row for masked positions
#define NWARP  16                    // warps per gather block
#define WPOS   (SEQ / NWARP)         // 16 positions per warp

// fp16 transposed log-weight table, rows padded to 256B:
// T[d][v] = log(max(2*sigmoid(raw[v][d]), 1e-8)) for v<96, 0 for pad.
// (DEND+1) rows -> ~6.3 MB, L2 resident. 256B row = exactly 2 cache lines.
__device__ __align__(256) __half g_logw[(DEND + 1) * VPAD];

// ---------------------------------------------------------------------------
// Kernel A: fused sigmoid/log + transpose into padded rows.
// grid (768, 3), block (32, 8). y==2 tile also zeros the pad columns.
// ---------------------------------------------------------------------------
__global__ void prep_kernel(const float* __restrict__ raw) {
    __shared__ float tile[32][33];
    const int d0 = blockIdx.x * 32;
    const int v0 = blockIdx.y * 32;
    const int tx = threadIdx.x, ty = threadIdx.y;

    #pragma unroll
    for (int i = ty; i < 32; i += 8) {
        float x = raw[(v0 + i) * DEND + (d0 + tx)];
        float w = 2.0f * __frcp_rn(1.0f + __expf(-x));
        w = fmaxf(w, 1e-8f);
        tile[i][tx] = __logf(w);
    }
    __syncthreads();
    #pragma unroll
    for (int i = ty; i < 32; i += 8) {
        g_logw[(d0 + i) * VPAD + (v0 + tx)] = __float2half_rn(tile[tx][i]);
    }
    // pad columns 96..127 zeroed by the y==2 tile for its 32 d-rows
    if (blockIdx.y == 2) {
        #pragma unroll
        for (int i = ty; i < 32; i += 8)
            g_logw[(d0 + i) * VPAD + 96 + tx] = __float2half_rn(0.0f);
    }
    // full zero row for masked positions
    if (blockIdx.x == 0 && blockIdx.y == 0) {
        const int t = ty * 32 + tx;
        if (t < VPAD) g_logw[ZROW * VPAD + t] = __float2half_rn(0.0f);
    }
}

// ---------------------------------------------------------------------------
// Kernel B: one sample per block, 512 threads (16 warps).
// Warp w handles positions [16w, 16w+16). For each position the whole warp
// loads one padded 256B row: lane l takes uint2 (4 halves) -> exactly two
// aligned 128B lines per LDG.64. fp16 accumulate in chains of 8, fp32 spill.
// ---------------------------------------------------------------------------
__global__ void __launch_bounds__(32 * NWARP)
gather_kernel(const int* __restrict__ chars,
              float* __restrict__ out) {
    __shared__ int   offs[SEQ];                  // uint2-unit row base offsets
    __shared__ float part[NWARP][32][4];         // 8 KB partials
    __shared__ int   nact_s;

    const int b = blockIdx.x;
    const int t = threadIdx.x;                   // 0..511

    if (t == 0) nact_s = 0;
    __syncthreads();

    if (t < SEQ) {
        const int c = chars[b * SEQ + t];
        const bool act = (c > 0);
        const int dend = act ? (t * VOC + c - 1) : ZROW;
        offs[t] = dend * (VPAD / 4);             // uint2 units per row = 32
        const unsigned m = __ballot_sync(0xffffffffu, act);
        if ((t & 31) == 0) atomicAdd(&nact_s, __popc(m));
    }
    __syncthreads();

    const int lane = t & 31;
    const int w    = t >> 5;
    const int s0   = w * WPOS;
    const uint2* __restrict__ base = (const uint2*)g_logw;

    const __half2 z = __float2half2_rn(0.0f);
    float f0 = 0.f, f1 = 0.f, f2 = 0.f, f3 = 0.f;

    #pragma unroll
    for (int g = 0; g < WPOS; g += 8) {          // 2 groups of 8 (fp16 chains)
        __half2 aLo = z, aHi = z, bLo = z, bHi = z;
        #pragma unroll
        for (int i = 0; i < 8; i += 2) {
            const int oa = offs[s0 + g + i];
            const int ob = offs[s0 + g + i + 1];
            const uint2 ua = base[oa + lane];
            const uint2 ub = base[ob + lane];
            aLo = __hadd2(aLo, *(const __half2*)&ua.x);
            aHi = __hadd2(aHi, *(const __half2*)&ua.y);
            bLo = __hadd2(bLo, *(const __half2*)&ub.x);
            bHi = __hadd2(bHi, *(const __half2*)&ub.y);
        }
        const float2 pLo = __half22float2(aLo);
        const float2 pHi = __half22float2(aHi);
        const float2 qLo = __half22float2(bLo);
        const float2 qHi = __half22float2(bHi);
        f0 += pLo.x + qLo.x;
        f1 += pLo.y + qLo.y;
        f2 += pHi.x + qHi.x;
        f3 += pHi.y + qHi.y;
    }

    part[w][lane][0] = f0;
    part[w][lane][1] = f1;
    part[w][lane][2] = f2;
    part[w][lane][3] = f3;
    __syncthreads();

    // Final reduce: lane t sums its 4 vocab entries across 16 warps.
    if (t < 24) {                                // 24 lanes * 4 = 96 vocab
        float sx = 0.f, sy = 0.f, sz = 0.f, sw = 0.f;
        #pragma unroll
        for (int k = 0; k < NWARP; k++) {
            sx += part[k][t][0];
            sy += part[k][t][1];
            sz += part[k][t][2];
            sw += part[k][t][3];
        }
        const float inv = __frcp_rn((float)max(nact_s, 1));
        float4 r;
        r.x = __expf(sx * inv);
        r.y = __expf(sy * inv);
        r.z = __expf(sz * inv);
        r.w = __expf(sw * inv);
        ((float4*)(out + b * VOC))[t] = r;
    }
}

// ---------------------------------------------------------------------------
extern "C" void kernel_launch(void* const* d_in, const int* in_sizes, int n_in,
                              void* d_out, int out_size) {
    const int*   chars = (const int*)d_in[0];     // (B, 256) int32
    const float* raw   = (const float*)d_in[1];   // (96, 24576) float32
    float*       out   = (float*)d_out;           // (B, 96) float32

    const int batch = in_sizes[0] / SEQ;

    dim3 pgrid(DEND / 32, VOC / 32);              // (768, 3)
    dim3 pblk(32, 8);
    prep_kernel<<<pgrid, pblk>>>(raw);

    gather_kernel<<<batch, 32 * NWARP>>>(chars, out);
}